// round 14
// baseline (speedup 1.0000x reference)
#include <cuda_runtime.h>
#include <cuda_fp16.h>
#include <cstdint>

// Problem constants
#define Bz 4
#define Tt 8192
#define Cc 1024
#define Hh 16
#define Dd 64
#define Mtot (Bz * Tt)          // 32768

// ---------------- scratch (static __device__, no allocations) ----------------
__device__ __half g_xh[(size_t)Mtot * Cc];
__device__ __half g_qkvh[3][(size_t)Mtot * Cc];   // fp16 q,k,v (q,k post-softmax)
__device__ __half g_ah[(size_t)Mtot * Cc];        // attention output fp16
__device__ __half g_wh[4][(size_t)Cc * Cc];       // Wq,Wk,Wv contiguous; Wp last
__device__ float  g_bcat[3 * Cc];
__device__ float  g_ctx[Bz * Hh * Dd * Dd];       // TRANSPOSED: [bh][e][d]
__device__ float  g_ksum[Bz * Hh * Dd];

// ==================== helpers =====================
__device__ __forceinline__ uint32_t smem_u32(const void* p) {
    uint32_t a;
    asm("{ .reg .u64 t; cvta.to.shared.u64 t, %1; cvt.u32.u64 %0, t; }" : "=r"(a) : "l"(p));
    return a;
}

#define LDM_X4(r0, r1, r2, r3, addr)                                          \
    asm volatile("ldmatrix.sync.aligned.m8n8.x4.shared.b16 {%0,%1,%2,%3}, [%4];" \
                 : "=r"(r0), "=r"(r1), "=r"(r2), "=r"(r3) : "r"(addr))

#define LDM_X4_T(r0, r1, r2, r3, addr)                                        \
    asm volatile("ldmatrix.sync.aligned.m8n8.x4.trans.shared.b16 {%0,%1,%2,%3}, [%4];" \
                 : "=r"(r0), "=r"(r1), "=r"(r2), "=r"(r3) : "r"(addr))

#define MMA_F16(c, a0, a1, a2, a3, b0, b1)                                    \
    asm volatile(                                                             \
        "mma.sync.aligned.m16n8k16.row.col.f32.f16.f16.f32 "                  \
        "{%0,%1,%2,%3}, {%4,%5,%6,%7}, {%8,%9}, {%0,%1,%2,%3};"               \
        : "+f"((c)[0]), "+f"((c)[1]), "+f"((c)[2]), "+f"((c)[3])              \
        : "r"(a0), "r"(a1), "r"(a2), "r"(a3), "r"(b0), "r"(b1))

#define CP_ASYNC16(dst, src)                                                  \
    asm volatile("cp.async.ca.shared.global [%0], [%1], 16;" :: "r"(dst), "l"(src))
#define CP_COMMIT() asm volatile("cp.async.commit_group;" ::: "memory")
#define CP_WAIT2()  asm volatile("cp.async.wait_group 2;" ::: "memory")

// ---------------- fp32 -> fp16 convert for x (4 float4 / thread, MLP=4) ------
__global__ __launch_bounds__(256)
void f2h_x(const float* __restrict__ in, __half* __restrict__ out, int n4)
{
    int base = (blockIdx.x * blockDim.x + threadIdx.x) * 4;
    if (base + 3 < n4) {
        float4 v0 = ((const float4*)in)[base + 0];
        float4 v1 = ((const float4*)in)[base + 1];
        float4 v2 = ((const float4*)in)[base + 2];
        float4 v3 = ((const float4*)in)[base + 3];
        uint2 u0, u1, u2, u3;
        __half2 h;
        h = __floats2half2_rn(v0.x, v0.y); u0.x = *(uint32_t*)&h;
        h = __floats2half2_rn(v0.z, v0.w); u0.y = *(uint32_t*)&h;
        h = __floats2half2_rn(v1.x, v1.y); u1.x = *(uint32_t*)&h;
        h = __floats2half2_rn(v1.z, v1.w); u1.y = *(uint32_t*)&h;
        h = __floats2half2_rn(v2.x, v2.y); u2.x = *(uint32_t*)&h;
        h = __floats2half2_rn(v2.z, v2.w); u2.y = *(uint32_t*)&h;
        h = __floats2half2_rn(v3.x, v3.y); u3.x = *(uint32_t*)&h;
        h = __floats2half2_rn(v3.z, v3.w); u3.y = *(uint32_t*)&h;
        ((uint2*)out)[base + 0] = u0;
        ((uint2*)out)[base + 1] = u1;
        ((uint2*)out)[base + 2] = u2;
        ((uint2*)out)[base + 3] = u3;
    }
}

// prep: convert all 4 weight matrices + pack biases + zero ctx/ksum.
// Launch with >= 4*wn4 threads (wn4 = Cc*Cc/4).
__global__ __launch_bounds__(256)
void prep_kernel(const float* __restrict__ w0, const float* __restrict__ w1,
                 const float* __restrict__ w2, const float* __restrict__ w3,
                 __half* __restrict__ out, int wn4,
                 const float* __restrict__ bq, const float* __restrict__ bk,
                 const float* __restrict__ bv)
{
    int i = blockIdx.x * blockDim.x + threadIdx.x;
    if (i < 4 * wn4) {
        int sel = i / wn4;
        int j = i - sel * wn4;
        const float* src = (sel == 0) ? w0 : (sel == 1) ? w1 : (sel == 2) ? w2 : w3;
        float4 v = ((const float4*)src)[j];
        __half2 h0 = __floats2half2_rn(v.x, v.y);
        __half2 h1 = __floats2half2_rn(v.z, v.w);
        uint2 u;
        u.x = *(uint32_t*)&h0;
        u.y = *(uint32_t*)&h1;
        ((uint2*)out)[i] = u;
    }
    if (i < 3 * Cc) {
        float v = (i < Cc) ? bq[i] : (i < 2 * Cc ? bk[i - Cc] : bv[i - 2 * Cc]);
        g_bcat[i] = v;
    }
    if (i < Bz * Hh * Dd * Dd) g_ctx[i] = 0.0f;
    if (i < Bz * Hh * Dd)      g_ksum[i] = 0.0f;
}

// =============== FP16 GEMM (cp.async 4-stage): out = A @ W^T + bias ==========
// Tile 128(M) x 256(N), BK=32, 512 threads = 16 warps as 4(m) x 4(n),
// warp tile 32 x 64 (n-width = one head for fused softmax).   [Round 9 proven]
#define GBM 128
#define GBN 256
#define GBK 32
#define SSTR 40
#define A_BUF_B (GBM * SSTR * 2)     // 10240 bytes / stage
#define B_BUF_B (GBN * SSTR * 2)     // 20480 bytes / stage
#define NSTAGES 4
#define GEMM_SMEM_BYTES (NSTAGES * (A_BUF_B + B_BUF_B))   // 122880

__global__ void __launch_bounds__(512, 1)
gemm_cp(const __half* __restrict__ A, const __half* __restrict__ W,
        const float* __restrict__ bias,
        __half* __restrict__ outH, float* __restrict__ outF, int qkv_mode)
{
    extern __shared__ __half sm[];
    const int K = Cc;

    const int tid  = threadIdx.x;
    const int lane = tid & 31;
    const int warp = tid >> 5;
    const int gid  = lane >> 2;
    const int tig  = lane & 3;

    const int bm = blockIdx.y * GBM;
    const int bn = blockIdx.x * GBN;

    const int wm = (warp >> 2) * 32;
    const int wn = (warp & 3) * 64;

    const int lrow = tid >> 2;         // 0..127
    const int lcol = (tid & 3) * 8;    // halfs 0,8,16,24

    const __half* Ag = A + (size_t)(bm + lrow) * K + lcol;
    const __half* Wg = W + (size_t)(bn + lrow) * K + lcol;

    const uint32_t sA = smem_u32(sm);
    const uint32_t sB = sA + NSTAGES * A_BUF_B;
    const uint32_t dA  = sA + (uint32_t)((lrow * SSTR + lcol) * 2);
    const uint32_t dB0 = sB + (uint32_t)((lrow * SSTR + lcol) * 2);
    const uint32_t dB1 = sB + (uint32_t)(((lrow + 128) * SSTR + lcol) * 2);

    const int blk = lane >> 3;
    const int rib = lane & 7;
    const uint32_t aBase = sA + (uint32_t)(((wm + (blk & 1) * 8 + rib) * SSTR
                                            + (blk >> 1) * 8) * 2);
    const uint32_t bBase = sB + (uint32_t)(((wn + (blk >> 1) * 8 + rib) * SSTR
                                            + (blk & 1) * 8) * 2);

    float acc[2][8][4] = {};

    // prologue: stages 0,1,2
    #pragma unroll
    for (int s = 0; s < 3; ++s) {
        const int k0 = s * GBK;
        CP_ASYNC16(dA + s * A_BUF_B, Ag + k0);
        CP_ASYNC16(dB0 + s * B_BUF_B, Wg + k0);
        CP_ASYNC16(dB1 + s * B_BUF_B, Wg + (size_t)128 * K + k0);
        CP_COMMIT();
    }
    CP_WAIT2();
    __syncthreads();

    const int NST = K / GBK;   // 32
    for (int s = 0; s < NST; ++s) {
        const int buf = s % NSTAGES;

        if (s + 3 < NST) {
            const int ns = (s + 3) % NSTAGES;
            const int k0 = (s + 3) * GBK;
            CP_ASYNC16(dA + ns * A_BUF_B, Ag + k0);
            CP_ASYNC16(dB0 + ns * B_BUF_B, Wg + k0);
            CP_ASYNC16(dB1 + ns * B_BUF_B, Wg + (size_t)128 * K + k0);
        }
        CP_COMMIT();

        const uint32_t aOff = aBase + buf * A_BUF_B;
        const uint32_t bOff = bBase + buf * B_BUF_B;

        #pragma unroll
        for (int kk = 0; kk < GBK; kk += 16) {
            uint32_t af[2][4];
            #pragma unroll
            for (int mt = 0; mt < 2; ++mt)
                LDM_X4(af[mt][0], af[mt][1], af[mt][2], af[mt][3],
                       aOff + (uint32_t)((mt * 16 * SSTR + kk) * 2));

            uint32_t bf[4][4];
            #pragma unroll
            for (int p = 0; p < 4; ++p)
                LDM_X4(bf[p][0], bf[p][1], bf[p][2], bf[p][3],
                       bOff + (uint32_t)((p * 16 * SSTR + kk) * 2));

            #pragma unroll
            for (int mt = 0; mt < 2; ++mt) {
                #pragma unroll
                for (int p = 0; p < 4; ++p) {
                    MMA_F16(acc[mt][2 * p],     af[mt][0], af[mt][1], af[mt][2], af[mt][3],
                            bf[p][0], bf[p][1]);
                    MMA_F16(acc[mt][2 * p + 1], af[mt][0], af[mt][1], af[mt][2], af[mt][3],
                            bf[p][2], bf[p][3]);
                }
            }
        }

        CP_WAIT2();
        __syncthreads();
    }

    // ---- epilogue ----
    float bcol[8][2];
    #pragma unroll
    for (int nt = 0; nt < 8; ++nt) {
        const int c0 = bn + wn + nt * 8 + tig * 2;
        bcol[nt][0] = bias[c0];
        bcol[nt][1] = bias[c0 + 1];
    }

    const int mat = bn >> 10;                         // which of q/k/v (mode 1)
    const bool do_sm = qkv_mode && (mat < 2);
    const int ncol0 = (qkv_mode ? (bn & 1023) : bn) + wn;

    #pragma unroll
    for (int mt = 0; mt < 2; ++mt) {
        #pragma unroll
        for (int nt = 0; nt < 8; ++nt) {
            acc[mt][nt][0] += bcol[nt][0];
            acc[mt][nt][1] += bcol[nt][1];
            acc[mt][nt][2] += bcol[nt][0];
            acc[mt][nt][3] += bcol[nt][1];
        }

        if (do_sm) {
            float mlo = -1e30f, mhi = -1e30f;
            #pragma unroll
            for (int nt = 0; nt < 8; ++nt) {
                mlo = fmaxf(mlo, fmaxf(acc[mt][nt][0], acc[mt][nt][1]));
                mhi = fmaxf(mhi, fmaxf(acc[mt][nt][2], acc[mt][nt][3]));
            }
            mlo = fmaxf(mlo, __shfl_xor_sync(0xffffffffu, mlo, 1));
            mlo = fmaxf(mlo, __shfl_xor_sync(0xffffffffu, mlo, 2));
            mhi = fmaxf(mhi, __shfl_xor_sync(0xffffffffu, mhi, 1));
            mhi = fmaxf(mhi, __shfl_xor_sync(0xffffffffu, mhi, 2));

            float slo = 0.0f, shi = 0.0f;
            #pragma unroll
            for (int nt = 0; nt < 8; ++nt) {
                acc[mt][nt][0] = __expf(acc[mt][nt][0] - mlo);
                acc[mt][nt][1] = __expf(acc[mt][nt][1] - mlo);
                acc[mt][nt][2] = __expf(acc[mt][nt][2] - mhi);
                acc[mt][nt][3] = __expf(acc[mt][nt][3] - mhi);
                slo += acc[mt][nt][0] + acc[mt][nt][1];
                shi += acc[mt][nt][2] + acc[mt][nt][3];
            }
            slo += __shfl_xor_sync(0xffffffffu, slo, 1);
            slo += __shfl_xor_sync(0xffffffffu, slo, 2);
            shi += __shfl_xor_sync(0xffffffffu, shi, 1);
            shi += __shfl_xor_sync(0xffffffffu, shi, 2);
            const float ilo = 1.0f / slo, ihi = 1.0f / shi;
            #pragma unroll
            for (int nt = 0; nt < 8; ++nt) {
                acc[mt][nt][0] *= ilo;
                acc[mt][nt][1] *= ilo;
                acc[mt][nt][2] *= ihi;
                acc[mt][nt][3] *= ihi;
            }
        }

        const int r0 = bm + wm + mt * 16 + gid;
        if (qkv_mode) {
            __half* oB = outH + (size_t)mat * ((size_t)Mtot * Cc);
            #pragma unroll
            for (int nt = 0; nt < 8; ++nt) {
                const int c0 = ncol0 + nt * 8 + tig * 2;
                __half2 h0 = __floats2half2_rn(acc[mt][nt][0], acc[mt][nt][1]);
                __half2 h1 = __floats2half2_rn(acc[mt][nt][2], acc[mt][nt][3]);
                *(__half2*)(oB + (size_t)r0 * Cc + c0)       = h0;
                *(__half2*)(oB + (size_t)(r0 + 8) * Cc + c0) = h1;
            }
        } else {
            #pragma unroll
            for (int nt = 0; nt < 8; ++nt) {
                const int c0 = ncol0 + nt * 8 + tig * 2;
                float2 o0, o1;
                o0.x = acc[mt][nt][0]; o0.y = acc[mt][nt][1];
                o1.x = acc[mt][nt][2]; o1.y = acc[mt][nt][3];
                *(float2*)(outF + (size_t)r0 * Cc + c0)       = o0;
                *(float2*)(outF + (size_t)(r0 + 8) * Cc + c0) = o1;
            }
        }
    }
}

// ---- context via tensor cores: ctxT[e][d] = sum_t v[t][e] k[t][d] ----------
#define CSPLIT 16

__global__ __launch_bounds__(128)
void context_mma(const __half* __restrict__ k, const __half* __restrict__ v)
{
    __shared__ __align__(16) __half ks[16][72];
    __shared__ __align__(16) __half vs[16][72];

    const int tid  = threadIdx.x;
    const int lane = tid & 31;
    const int warp = tid >> 5;
    const int gid  = lane >> 2;
    const int tig  = lane & 3;

    const int bh = blockIdx.y;
    const int b  = bh >> 4;
    const int h  = bh & 15;
    const int tBase = blockIdx.x * (Tt / CSPLIT);

    const int lrow = tid >> 3;        // 0..15
    const int lcol = (tid & 7) * 8;   // 0..56

    const int e0  = warp * 16;
    const int blk = lane >> 3;
    const int rib = lane & 7;

    const uint32_t sK = smem_u32(&ks[0][0]);
    const uint32_t sV = smem_u32(&vs[0][0]);
    const uint32_t aAddr = sV + (uint32_t)(((((blk >> 1) * 8) + rib) * 72
                                            + e0 + (blk & 1) * 8) * 2);
    const uint32_t bAddr = sK + (uint32_t)(((((blk & 1) * 8) + rib) * 72
                                            + (blk >> 1) * 8) * 2);

    float acc[8][4] = {};
    float ksacc = 0.0f;

    const int NCH = (Tt / CSPLIT) / 16;   // 32
    for (int c = 0; c < NCH; ++c) {
        const int t = tBase + c * 16 + lrow;
        const size_t off = ((size_t)(b * Tt + t)) * Cc + h * 64 + lcol;
        *(uint4*)&ks[lrow][lcol] = *(const uint4*)(k + off);
        *(uint4*)&vs[lrow][lcol] = *(const uint4*)(v + off);
        __syncthreads();

        if (tid < 64) {
            #pragma unroll
            for (int tt = 0; tt < 16; ++tt)
                ksacc += __half2float(ks[tt][tid]);
        }

        uint32_t af[4];
        LDM_X4_T(af[0], af[1], af[2], af[3], aAddr);
        uint32_t bf[4][4];
        #pragma unroll
        for (int p = 0; p < 4; ++p)
            LDM_X4_T(bf[p][0], bf[p][1], bf[p][2], bf[p][3],
                     bAddr + (uint32_t)(p * 16 * 2));

        #pragma unroll
        for (int p = 0; p < 4; ++p) {
            MMA_F16(acc[2 * p],     af[0], af[1], af[2], af[3], bf[p][0], bf[p][1]);
            MMA_F16(acc[2 * p + 1], af[0], af[1], af[2], af[3], bf[p][2], bf[p][3]);
        }
        __syncthreads();
    }

    float* ctx = g_ctx + (size_t)bh * 4096;
    #pragma unroll
    for (int nt = 0; nt < 8; ++nt) {
        const int d = nt * 8 + tig * 2;
        atomicAdd(&ctx[(e0 + gid) * 64 + d],         acc[nt][0]);
        atomicAdd(&ctx[(e0 + gid) * 64 + d + 1],     acc[nt][1]);
        atomicAdd(&ctx[(e0 + gid + 8) * 64 + d],     acc[nt][2]);
        atomicAdd(&ctx[(e0 + gid + 8) * 64 + d + 1], acc[nt][3]);
    }
    if (tid < 64) atomicAdd(&g_ksum[bh * 64 + tid], ksacc);
}

// ------- attn_out via tensor cores: ah = fp16((q @ ctx) * Dinv + q) ----------
// Per CTA: 128 q-rows x 64 cols of one (b,h). 128 threads = 4 warps,
// warp tile 32(m) x 64(n), K = 64 in 4 steps of 16.
// ctx is read as fp32 and converted to fp16 inline while staging to smem.
#define QSTR 72     // halfs per row in smem (64 + 8 pad)
#define AO_SMEM_BYTES (128 * QSTR * 2 + 64 * QSTR * 2 + 64 * 4 + 128 * 4)

__global__ __launch_bounds__(128)
void attn_out_mma(const __half* __restrict__ q, __half* __restrict__ ah)
{
    extern __shared__ char smc[];
    __half* qs   = (__half*)smc;                        // [128][QSTR]
    __half* cs   = qs + 128 * QSTR;                     // [64][QSTR]  (ctxT rows e)
    float*  ksum = (float*)(cs + 64 * QSTR);            // [64]
    float*  dinv = ksum + 64;                           // [128]

    const int tid  = threadIdx.x;
    const int lane = tid & 31;
    const int warp = tid >> 5;
    const int gid  = lane >> 2;
    const int tig  = lane & 3;

    const int b  = blockIdx.z;
    const int h  = blockIdx.y;
    const int t0 = blockIdx.x * 128;
    const int bh = b * Hh + h;

    // load q tile: thread r loads its full row (64 halfs = 8 uint4)
    {
        const __half* qp = q + ((size_t)(b * Tt + t0 + tid)) * Cc + h * 64;
        #pragma unroll
        for (int j = 0; j < 8; ++j)
            *(uint4*)&qs[tid * QSTR + j * 8] = *(const uint4*)(qp + j * 8);
    }
    // load ctxT (fp32) and convert to fp16: thread loads half a row (32 floats)
    {
        int r = tid >> 1;
        int hhf = (tid & 1) * 32;
        const float* cp = g_ctx + (size_t)bh * 4096 + r * 64 + hhf;
        #pragma unroll
        for (int j = 0; j < 4; ++j) {
            float4 f0 = *(const float4*)(cp + j * 8);
            float4 f1 = *(const float4*)(cp + j * 8 + 4);
            __half2 h0 = __floats2half2_rn(f0.x, f0.y);
            __half2 h1 = __floats2half2_rn(f0.z, f0.w);
            __half2 h2 = __floats2half2_rn(f1.x, f1.y);
            __half2 h3 = __floats2half2_rn(f1.z, f1.w);
            uint4 u;
            u.x = *(uint32_t*)&h0; u.y = *(uint32_t*)&h1;
            u.z = *(uint32_t*)&h2; u.w = *(uint32_t*)&h3;
            *(uint4*)&cs[r * QSTR + hhf + j * 8] = u;
        }
    }
    if (tid < 64) ksum[tid] = g_ksum[bh * 64 + tid];
    __syncthreads();

    // dinv[r] = 1 / sum_d q[r][d]*ksum[d]
    {
        float s = 0.0f;
        #pragma unroll
        for (int d = 0; d < 64; ++d)
            s = fmaf(__half2float(qs[tid * QSTR + d]), ksum[d], s);
        dinv[tid] = 1.0f / s;
    }
    __syncthreads();

    const uint32_t sQ = smem_u32(qs);
    const uint32_t sC = smem_u32(cs);
    const int wm = warp * 32;

    const int blk = lane >> 3;
    const int rib = lane & 7;
    const uint32_t aBase = sQ + (uint32_t)(((wm + (blk & 1) * 8 + rib) * QSTR
                                            + (blk >> 1) * 8) * 2);
    const uint32_t bBase = sC + (uint32_t)((((blk >> 1) * 8 + rib) * QSTR
                                            + (blk & 1) * 8) * 2);

    float acc[2][8][4] = {};

    #pragma unroll
    for (int kk = 0; kk < 64; kk += 16) {
        uint32_t af[2][4];
        #pragma unroll
        for (int mt = 0; mt < 2; ++mt)
            LDM_X4(af[mt][0], af[mt][1], af[mt][2], af[mt][3],
                   aBase + (uint32_t)((mt * 16 * QSTR + kk) * 2));

        uint32_t bf[4][4];
        #pragma unroll
        for (int p = 0; p < 4; ++p)
            LDM_X4(bf[p][0], bf[p][1], bf[p][2], bf[p][3],
                   bBase + (uint32_t)((p * 16 * QSTR + kk) * 2));

        #pragma unroll
        for (int mt = 0; mt < 2; ++mt) {
            #pragma unroll
            for (int p = 0; p < 4; ++p) {
                MMA_F16(acc[mt][2 * p],     af[mt][0], af[mt][1], af[mt][2], af[mt][3],
                        bf[p][0], bf[p][1]);
                MMA_F16(acc[mt][2 * p + 1], af[mt][0], af[mt][1], af[mt][2], af[mt][3],
                        bf[p][2], bf[p][3]);
            }
        }
    }

    // epilogue: out = acc * dinv[row] + q[row][col], fp16 store
    #pragma unroll
    for (int mt = 0; mt < 2; ++mt) {
        const int r0 = wm + mt * 16 + gid;     // local rows r0, r0+8
        const float di0 = dinv[r0];
        const float di1 = dinv[r0 + 8];
        __half* o0 = ah + ((size_t)(b * Tt + t0 + r0)) * Cc + h * 64;
        __half* o1 = ah + ((size_t)(b * Tt + t0 + r0 + 8)) * Cc + h * 64;
        #pragma unroll
        for (int nt = 0; nt < 8; ++nt) {
            const int c0 = nt * 8 + tig * 2;
            float q00 = __half2float(qs[r0 * QSTR + c0]);
            float q01 = __half2float(qs[r0 * QSTR + c0 + 1]);
            float q10 = __half2float(qs[(r0 + 8) * QSTR + c0]);
            float q11 = __half2float(qs[(r0 + 8) * QSTR + c0 + 1]);
            __half2 h0 = __floats2half2_rn(fmaf(acc[mt][nt][0], di0, q00),
                                           fmaf(acc[mt][nt][1], di0, q01));
            __half2 h1 = __floats2half2_rn(fmaf(acc[mt][nt][2], di1, q10),
                                           fmaf(acc[mt][nt][3], di1, q11));
            *(__half2*)(o0 + c0) = h0;
            *(__half2*)(o1 + c0) = h1;
        }
    }
}

// ---------------- launcher ----------------------------------------------------
extern "C" void kernel_launch(void* const* d_in, const int* in_sizes, int n_in,
                              void* d_out, int out_size)
{
    (void)in_sizes; (void)n_in; (void)out_size;

    const float* x  = (const float*)d_in[0];
    const float* Wq = (const float*)d_in[1];
    const float* bq = (const float*)d_in[2];
    const float* Wk = (const float*)d_in[3];
    const float* bk = (const float*)d_in[4];
    const float* Wv = (const float*)d_in[5];
    const float* bv = (const float*)d_in[6];
    const float* Wp = (const float*)d_in[7];
    const float* bp = (const float*)d_in[8];
    float* out = (float*)d_out;

    __half *xh, *qkvh, *ah, *wh;
    float* bcat;
    cudaGetSymbolAddress((void**)&xh, g_xh);
    cudaGetSymbolAddress((void**)&qkvh, g_qkvh);
    cudaGetSymbolAddress((void**)&ah, g_ah);
    cudaGetSymbolAddress((void**)&wh, g_wh);
    cudaGetSymbolAddress((void**)&bcat, g_bcat);

    __half* whq = wh;                              // Wq,Wk,Wv contiguous
    __half* whp = wh + (size_t)3 * Cc * Cc;

    __half* qh = qkvh;
    __half* kh = qkvh + (size_t)Mtot * Cc;
    __half* vh = qkvh + (size_t)2 * Mtot * Cc;

    cudaFuncSetAttribute(gemm_cp, cudaFuncAttributeMaxDynamicSharedMemorySize,
                         GEMM_SMEM_BYTES);
    cudaFuncSetAttribute(attn_out_mma, cudaFuncAttributeMaxDynamicSharedMemorySize,
                         AO_SMEM_BYTES);

    const int xn4 = (Mtot * Cc) / 4;               // 8388608 float4
    const int wn4 = (Cc * Cc) / 4;                 // 262144 float4
    f2h_x<<<xn4 / (256 * 4), 256>>>(x, xh, xn4);   // 4 float4 per thread
    prep_kernel<<<(4 * wn4) / 256, 256>>>(Wq, Wk, Wv, Wp, wh, wn4, bq, bk, bv);

    // fused QKV GEMM: N = 3072
    gemm_cp<<<dim3(3 * Cc / GBN, Mtot / GBM), 512, GEMM_SMEM_BYTES>>>(
        xh, whq, bcat, qkvh, nullptr, 1);

    context_mma<<<dim3(CSPLIT, Bz * Hh), 128>>>(kh, vh);

    attn_out_mma<<<dim3(Tt / 128, Hh, Bz), 128, AO_SMEM_BYTES>>>(qh, ah);

    // output projection: N = 1024, fp32 out
    gemm_cp<<<dim3(Cc / GBN, Mtot / GBM), 512, GEMM_SMEM_BYTES>>>(
        ah, whp, bp, nullptr, out, 0);
}

// round 15
// speedup vs baseline: 1.0216x; 1.0216x over previous
#include <cuda_runtime.h>
#include <cuda_fp16.h>
#include <cstdint>

// Problem constants
#define Bz 4
#define Tt 8192
#define Cc 1024
#define Hh 16
#define Dd 64
#define Mtot (Bz * Tt)          // 32768

// ---------------- scratch (static __device__, no allocations) ----------------
__device__ __half g_xh[(size_t)Mtot * Cc];
__device__ __half g_qkvh[3][(size_t)Mtot * Cc];   // fp16 q,k,v (q,k post-softmax)
__device__ __half g_ah[(size_t)Mtot * Cc];        // attention output fp16
__device__ __half g_wh[4][(size_t)Cc * Cc];       // Wq,Wk,Wv contiguous; Wp last
__device__ float  g_bcat[3 * Cc];
__device__ float  g_ctx[Bz * Hh * Dd * Dd];       // TRANSPOSED: [bh][e][d]
__device__ __half g_ctxh[Bz * Hh * Dd * Dd];      // fp16 copy of g_ctx
__device__ float  g_ksum[Bz * Hh * Dd];

// ==================== helpers =====================
__device__ __forceinline__ uint32_t smem_u32(const void* p) {
    uint32_t a;
    asm("{ .reg .u64 t; cvta.to.shared.u64 t, %1; cvt.u32.u64 %0, t; }" : "=r"(a) : "l"(p));
    return a;
}

#define LDM_X4(r0, r1, r2, r3, addr)                                          \
    asm volatile("ldmatrix.sync.aligned.m8n8.x4.shared.b16 {%0,%1,%2,%3}, [%4];" \
                 : "=r"(r0), "=r"(r1), "=r"(r2), "=r"(r3) : "r"(addr))

#define LDM_X4_T(r0, r1, r2, r3, addr)                                        \
    asm volatile("ldmatrix.sync.aligned.m8n8.x4.trans.shared.b16 {%0,%1,%2,%3}, [%4];" \
                 : "=r"(r0), "=r"(r1), "=r"(r2), "=r"(r3) : "r"(addr))

#define MMA_F16(c, a0, a1, a2, a3, b0, b1)                                    \
    asm volatile(                                                             \
        "mma.sync.aligned.m16n8k16.row.col.f32.f16.f16.f32 "                  \
        "{%0,%1,%2,%3}, {%4,%5,%6,%7}, {%8,%9}, {%0,%1,%2,%3};"               \
        : "+f"((c)[0]), "+f"((c)[1]), "+f"((c)[2]), "+f"((c)[3])              \
        : "r"(a0), "r"(a1), "r"(a2), "r"(a3), "r"(b0), "r"(b1))

#define CP_ASYNC16(dst, src)                                                  \
    asm volatile("cp.async.ca.shared.global [%0], [%1], 16;" :: "r"(dst), "l"(src))
#define CP_COMMIT() asm volatile("cp.async.commit_group;" ::: "memory")
#define CP_WAIT1()  asm volatile("cp.async.wait_group 1;" ::: "memory")
#define CP_WAIT2()  asm volatile("cp.async.wait_group 2;" ::: "memory")

// ---------------- fp32 -> fp16 bulk convert ----------------------------------
__global__ __launch_bounds__(256)
void f2h_kernel(const float* __restrict__ in, __half* __restrict__ out, int n4)
{
    int i = blockIdx.x * blockDim.x + threadIdx.x;
    if (i < n4) {
        float4 v = ((const float4*)in)[i];
        __half2 h0 = __floats2half2_rn(v.x, v.y);
        __half2 h1 = __floats2half2_rn(v.z, v.w);
        uint2 u;
        u.x = *(uint32_t*)&h0;
        u.y = *(uint32_t*)&h1;
        ((uint2*)out)[i] = u;
    }
}

// convert all 4 weight matrices in one launch: wsel = i / wn4
__global__ __launch_bounds__(256)
void f2h_weights(const float* __restrict__ w0, const float* __restrict__ w1,
                 const float* __restrict__ w2, const float* __restrict__ w3,
                 __half* __restrict__ out, int wn4)
{
    int i = blockIdx.x * blockDim.x + threadIdx.x;
    int sel = i / wn4;
    int j = i - sel * wn4;
    const float* src = (sel == 0) ? w0 : (sel == 1) ? w1 : (sel == 2) ? w2 : w3;
    float4 v = ((const float4*)src)[j];
    __half2 h0 = __floats2half2_rn(v.x, v.y);
    __half2 h1 = __floats2half2_rn(v.z, v.w);
    uint2 u;
    u.x = *(uint32_t*)&h0;
    u.y = *(uint32_t*)&h1;
    ((uint2*)out)[i] = u;
}

// pack biases AND zero the ctx/ksum accumulators.
// MUST be launched with >= Bz*Hh*Dd*Dd (=65536) threads.
__global__ void pack_bias(const float* __restrict__ bq, const float* __restrict__ bk,
                          const float* __restrict__ bv)
{
    int i = blockIdx.x * blockDim.x + threadIdx.x;
    if (i < 3 * Cc) {
        float v = (i < Cc) ? bq[i] : (i < 2 * Cc ? bk[i - Cc] : bv[i - 2 * Cc]);
        g_bcat[i] = v;
    }
    if (i < Bz * Hh * Dd * Dd) g_ctx[i] = 0.0f;
    if (i < Bz * Hh * Dd)      g_ksum[i] = 0.0f;
}

// ctx fp32 -> fp16 (after context accumulation)
__global__ __launch_bounds__(256)
void ctx_finalize()
{
    int i = blockIdx.x * blockDim.x + threadIdx.x;
    if (i < Bz * Hh * Dd * Dd)
        g_ctxh[i] = __float2half_rn(g_ctx[i]);
}

// =============== FP16 GEMM (cp.async 4-stage): out = A @ W^T + bias ==========
// Tile 128(M) x 256(N), BK=32, 512 threads = 16 warps as 4(m) x 4(n),
// warp tile 32 x 64 (n-width = one head for fused softmax).   [Round 9 proven]
#define GBM 128
#define GBN 256
#define GBK 32
#define SSTR 40
#define A_BUF_B (GBM * SSTR * 2)     // 10240 bytes / stage
#define B_BUF_B (GBN * SSTR * 2)     // 20480 bytes / stage
#define NSTAGES 4
#define GEMM_SMEM_BYTES (NSTAGES * (A_BUF_B + B_BUF_B))   // 122880

__global__ void __launch_bounds__(512, 1)
gemm_cp(const __half* __restrict__ A, const __half* __restrict__ W,
        const float* __restrict__ bias,
        __half* __restrict__ outH, float* __restrict__ outF, int qkv_mode)
{
    extern __shared__ __half sm[];
    const int K = Cc;

    const int tid  = threadIdx.x;
    const int lane = tid & 31;
    const int warp = tid >> 5;
    const int gid  = lane >> 2;
    const int tig  = lane & 3;

    const int bm = blockIdx.y * GBM;
    const int bn = blockIdx.x * GBN;

    const int wm = (warp >> 2) * 32;
    const int wn = (warp & 3) * 64;

    const int lrow = tid >> 2;         // 0..127
    const int lcol = (tid & 3) * 8;    // halfs 0,8,16,24

    const __half* Ag = A + (size_t)(bm + lrow) * K + lcol;
    const __half* Wg = W + (size_t)(bn + lrow) * K + lcol;

    const uint32_t sA = smem_u32(sm);
    const uint32_t sB = sA + NSTAGES * A_BUF_B;
    const uint32_t dA  = sA + (uint32_t)((lrow * SSTR + lcol) * 2);
    const uint32_t dB0 = sB + (uint32_t)((lrow * SSTR + lcol) * 2);
    const uint32_t dB1 = sB + (uint32_t)(((lrow + 128) * SSTR + lcol) * 2);

    const int blk = lane >> 3;
    const int rib = lane & 7;
    const uint32_t aBase = sA + (uint32_t)(((wm + (blk & 1) * 8 + rib) * SSTR
                                            + (blk >> 1) * 8) * 2);
    const uint32_t bBase = sB + (uint32_t)(((wn + (blk >> 1) * 8 + rib) * SSTR
                                            + (blk & 1) * 8) * 2);

    float acc[2][8][4] = {};

    // prologue: stages 0,1,2
    #pragma unroll
    for (int s = 0; s < 3; ++s) {
        const int k0 = s * GBK;
        CP_ASYNC16(dA + s * A_BUF_B, Ag + k0);
        CP_ASYNC16(dB0 + s * B_BUF_B, Wg + k0);
        CP_ASYNC16(dB1 + s * B_BUF_B, Wg + (size_t)128 * K + k0);
        CP_COMMIT();
    }
    CP_WAIT2();
    __syncthreads();

    const int NST = K / GBK;   // 32
    for (int s = 0; s < NST; ++s) {
        const int buf = s % NSTAGES;

        if (s + 3 < NST) {
            const int ns = (s + 3) % NSTAGES;
            const int k0 = (s + 3) * GBK;
            CP_ASYNC16(dA + ns * A_BUF_B, Ag + k0);
            CP_ASYNC16(dB0 + ns * B_BUF_B, Wg + k0);
            CP_ASYNC16(dB1 + ns * B_BUF_B, Wg + (size_t)128 * K + k0);
        }
        CP_COMMIT();

        const uint32_t aOff = aBase + buf * A_BUF_B;
        const uint32_t bOff = bBase + buf * B_BUF_B;

        #pragma unroll
        for (int kk = 0; kk < GBK; kk += 16) {
            uint32_t af[2][4];
            #pragma unroll
            for (int mt = 0; mt < 2; ++mt)
                LDM_X4(af[mt][0], af[mt][1], af[mt][2], af[mt][3],
                       aOff + (uint32_t)((mt * 16 * SSTR + kk) * 2));

            uint32_t bf[4][4];
            #pragma unroll
            for (int p = 0; p < 4; ++p)
                LDM_X4(bf[p][0], bf[p][1], bf[p][2], bf[p][3],
                       bOff + (uint32_t)((p * 16 * SSTR + kk) * 2));

            #pragma unroll
            for (int mt = 0; mt < 2; ++mt) {
                #pragma unroll
                for (int p = 0; p < 4; ++p) {
                    MMA_F16(acc[mt][2 * p],     af[mt][0], af[mt][1], af[mt][2], af[mt][3],
                            bf[p][0], bf[p][1]);
                    MMA_F16(acc[mt][2 * p + 1], af[mt][0], af[mt][1], af[mt][2], af[mt][3],
                            bf[p][2], bf[p][3]);
                }
            }
        }

        CP_WAIT2();
        __syncthreads();
    }

    // ---- epilogue ----
    float bcol[8][2];
    #pragma unroll
    for (int nt = 0; nt < 8; ++nt) {
        const int c0 = bn + wn + nt * 8 + tig * 2;
        bcol[nt][0] = bias[c0];
        bcol[nt][1] = bias[c0 + 1];
    }

    const int mat = bn >> 10;                         // which of q/k/v (mode 1)
    const bool do_sm = qkv_mode && (mat < 2);
    const int ncol0 = (qkv_mode ? (bn & 1023) : bn) + wn;

    #pragma unroll
    for (int mt = 0; mt < 2; ++mt) {
        #pragma unroll
        for (int nt = 0; nt < 8; ++nt) {
            acc[mt][nt][0] += bcol[nt][0];
            acc[mt][nt][1] += bcol[nt][1];
            acc[mt][nt][2] += bcol[nt][0];
            acc[mt][nt][3] += bcol[nt][1];
        }

        if (do_sm) {
            float mlo = -1e30f, mhi = -1e30f;
            #pragma unroll
            for (int nt = 0; nt < 8; ++nt) {
                mlo = fmaxf(mlo, fmaxf(acc[mt][nt][0], acc[mt][nt][1]));
                mhi = fmaxf(mhi, fmaxf(acc[mt][nt][2], acc[mt][nt][3]));
            }
            mlo = fmaxf(mlo, __shfl_xor_sync(0xffffffffu, mlo, 1));
            mlo = fmaxf(mlo, __shfl_xor_sync(0xffffffffu, mlo, 2));
            mhi = fmaxf(mhi, __shfl_xor_sync(0xffffffffu, mhi, 1));
            mhi = fmaxf(mhi, __shfl_xor_sync(0xffffffffu, mhi, 2));

            float slo = 0.0f, shi = 0.0f;
            #pragma unroll
            for (int nt = 0; nt < 8; ++nt) {
                acc[mt][nt][0] = __expf(acc[mt][nt][0] - mlo);
                acc[mt][nt][1] = __expf(acc[mt][nt][1] - mlo);
                acc[mt][nt][2] = __expf(acc[mt][nt][2] - mhi);
                acc[mt][nt][3] = __expf(acc[mt][nt][3] - mhi);
                slo += acc[mt][nt][0] + acc[mt][nt][1];
                shi += acc[mt][nt][2] + acc[mt][nt][3];
            }
            slo += __shfl_xor_sync(0xffffffffu, slo, 1);
            slo += __shfl_xor_sync(0xffffffffu, slo, 2);
            shi += __shfl_xor_sync(0xffffffffu, shi, 1);
            shi += __shfl_xor_sync(0xffffffffu, shi, 2);
            const float ilo = 1.0f / slo, ihi = 1.0f / shi;
            #pragma unroll
            for (int nt = 0; nt < 8; ++nt) {
                acc[mt][nt][0] *= ilo;
                acc[mt][nt][1] *= ilo;
                acc[mt][nt][2] *= ihi;
                acc[mt][nt][3] *= ihi;
            }
        }

        const int r0 = bm + wm + mt * 16 + gid;
        if (qkv_mode) {
            __half* oB = outH + (size_t)mat * ((size_t)Mtot * Cc);
            #pragma unroll
            for (int nt = 0; nt < 8; ++nt) {
                const int c0 = ncol0 + nt * 8 + tig * 2;
                __half2 h0 = __floats2half2_rn(acc[mt][nt][0], acc[mt][nt][1]);
                __half2 h1 = __floats2half2_rn(acc[mt][nt][2], acc[mt][nt][3]);
                *(__half2*)(oB + (size_t)r0 * Cc + c0)       = h0;
                *(__half2*)(oB + (size_t)(r0 + 8) * Cc + c0) = h1;
            }
        } else {
            #pragma unroll
            for (int nt = 0; nt < 8; ++nt) {
                const int c0 = ncol0 + nt * 8 + tig * 2;
                float2 o0, o1;
                o0.x = acc[mt][nt][0]; o0.y = acc[mt][nt][1];
                o1.x = acc[mt][nt][2]; o1.y = acc[mt][nt][3];
                *(float2*)(outF + (size_t)r0 * Cc + c0)       = o0;
                *(float2*)(outF + (size_t)(r0 + 8) * Cc + c0) = o1;
            }
        }
    }
}

// ---- context via tensor cores (cp.async 3-stage, 32 t-rows/stage) ----------
// ctxT[e][d] = sum_t v[t][e] k[t][d];  mma m=e, n=d, K=t (ldmatrix.trans).
// 128 threads = 4 warps; warp w covers e in [w*16, w*16+16), all 64 d.
#define CSPLIT 16
#define CTR 32                        // t-rows per stage
#define CST 72                        // smem stride (halfs)
#define CNS 3                         // stages
#define C_STAGE_B (CTR * CST * 2)     // 4608 bytes per tensor per stage

__global__ __launch_bounds__(128)
void context_mma(const __half* __restrict__ k, const __half* __restrict__ v)
{
    __shared__ __align__(16) __half ks[CNS][CTR][CST];
    __shared__ __align__(16) __half vs[CNS][CTR][CST];

    const int tid  = threadIdx.x;
    const int lane = tid & 31;
    const int warp = tid >> 5;
    const int gid  = lane >> 2;
    const int tig  = lane & 3;

    const int bh = blockIdx.y;
    const int b  = bh >> 4;
    const int h  = bh & 15;
    const int tBase = blockIdx.x * (Tt / CSPLIT);   // 512 rows per CTA

    // load mapping: 4 threads per 64-half row; thread covers 16 halfs (2x16B)
    const int lrow = tid >> 2;        // 0..31
    const int lcol = (tid & 3) * 16;  // 0,16,32,48

    const __half* kg = k + ((size_t)(b * Tt + tBase + lrow)) * Cc + h * 64 + lcol;
    const __half* vg = v + ((size_t)(b * Tt + tBase + lrow)) * Cc + h * 64 + lcol;
    const size_t stepG = (size_t)CTR * Cc;          // 32 rows ahead

    const uint32_t sK = smem_u32(&ks[0][0][0]);
    const uint32_t sV = smem_u32(&vs[0][0][0]);
    const uint32_t dK = sK + (uint32_t)((lrow * CST + lcol) * 2);
    const uint32_t dV = sV + (uint32_t)((lrow * CST + lcol) * 2);

    const int e0  = warp * 16;
    const int blk = lane >> 3;
    const int rib = lane & 7;
    // A = v^T: smem row t = (blk>>1)*8 + rib (+ sub*16), col e = e0 + (blk&1)*8
    const uint32_t aBase = sV + (uint32_t)(((((blk >> 1) * 8) + rib) * CST
                                            + e0 + (blk & 1) * 8) * 2);
    // B = k^T: smem row t = (blk&1)*8 + rib (+ sub*16), col d = (blk>>1)*8 (+ p*16)
    const uint32_t bBase = sK + (uint32_t)(((((blk & 1) * 8) + rib) * CST
                                            + (blk >> 1) * 8) * 2);

    float acc[8][4] = {};
    float ksacc = 0.0f;

    const int NCH = (Tt / CSPLIT) / CTR;   // 16

    // prologue: stages 0,1
    #pragma unroll
    for (int s = 0; s < 2; ++s) {
        CP_ASYNC16(dK + s * C_STAGE_B, kg + s * stepG);
        CP_ASYNC16(dK + s * C_STAGE_B + 16, kg + s * stepG + 8);
        CP_ASYNC16(dV + s * C_STAGE_B, vg + s * stepG);
        CP_ASYNC16(dV + s * C_STAGE_B + 16, vg + s * stepG + 8);
        CP_COMMIT();
    }
    CP_WAIT1();
    __syncthreads();

    for (int c = 0; c < NCH; ++c) {
        const int buf = c % CNS;

        if (c + 2 < NCH) {
            const int ns = (c + 2) % CNS;
            CP_ASYNC16(dK + ns * C_STAGE_B, kg + (size_t)(c + 2) * stepG);
            CP_ASYNC16(dK + ns * C_STAGE_B + 16, kg + (size_t)(c + 2) * stepG + 8);
            CP_ASYNC16(dV + ns * C_STAGE_B, vg + (size_t)(c + 2) * stepG);
            CP_ASYNC16(dV + ns * C_STAGE_B + 16, vg + (size_t)(c + 2) * stepG + 8);
        }
        CP_COMMIT();

        if (tid < 64) {
            #pragma unroll
            for (int tt = 0; tt < CTR; ++tt)
                ksacc += __half2float(ks[buf][tt][tid]);
        }

        #pragma unroll
        for (int sub = 0; sub < 2; ++sub) {
            const uint32_t subOff = (uint32_t)(buf * C_STAGE_B + sub * 16 * CST * 2);
            uint32_t af[4];
            LDM_X4_T(af[0], af[1], af[2], af[3], aBase + subOff);
            uint32_t bf[4][4];
            #pragma unroll
            for (int p = 0; p < 4; ++p)
                LDM_X4_T(bf[p][0], bf[p][1], bf[p][2], bf[p][3],
                         bBase + subOff + (uint32_t)(p * 16 * 2));

            #pragma unroll
            for (int p = 0; p < 4; ++p) {
                MMA_F16(acc[2 * p],     af[0], af[1], af[2], af[3], bf[p][0], bf[p][1]);
                MMA_F16(acc[2 * p + 1], af[0], af[1], af[2], af[3], bf[p][2], bf[p][3]);
            }
        }

        CP_WAIT1();
        __syncthreads();
    }

    float* ctx = g_ctx + (size_t)bh * 4096;
    #pragma unroll
    for (int nt = 0; nt < 8; ++nt) {
        const int d = nt * 8 + tig * 2;
        atomicAdd(&ctx[(e0 + gid) * 64 + d],         acc[nt][0]);
        atomicAdd(&ctx[(e0 + gid) * 64 + d + 1],     acc[nt][1]);
        atomicAdd(&ctx[(e0 + gid + 8) * 64 + d],     acc[nt][2]);
        atomicAdd(&ctx[(e0 + gid + 8) * 64 + d + 1], acc[nt][3]);
    }
    if (tid < 64) atomicAdd(&g_ksum[bh * 64 + tid], ksacc);
}

// ------- attn_out via tensor cores: ah = fp16((q @ ctx) * Dinv + q) ----------
// Per CTA: 128 q-rows x 64 cols of one (b,h). 128 threads = 4 warps,
// warp tile 32(m) x 64(n), K = 64 in 4 steps of 16.
#define QSTR 72     // halfs per row in smem (64 + 8 pad)
#define AO_SMEM_BYTES (128 * QSTR * 2 + 64 * QSTR * 2 + 64 * 4 + 128 * 4)

__global__ __launch_bounds__(128)
void attn_out_mma(const __half* __restrict__ q, __half* __restrict__ ah)
{
    extern __shared__ char smc[];
    __half* qs   = (__half*)smc;                        // [128][QSTR]
    __half* cs   = qs + 128 * QSTR;                     // [64][QSTR]  (ctxT rows e)
    float*  ksum = (float*)(cs + 64 * QSTR);            // [64]
    float*  dinv = ksum + 64;                           // [128]

    const int tid  = threadIdx.x;
    const int lane = tid & 31;
    const int warp = tid >> 5;
    const int gid  = lane >> 2;
    const int tig  = lane & 3;

    const int b  = blockIdx.z;
    const int h  = blockIdx.y;
    const int t0 = blockIdx.x * 128;
    const int bh = b * Hh + h;

    // load q tile: thread r loads its full row (64 halfs = 8 uint4)
    {
        const __half* qp = q + ((size_t)(b * Tt + t0 + tid)) * Cc + h * 64;
        #pragma unroll
        for (int j = 0; j < 8; ++j)
            *(uint4*)&qs[tid * QSTR + j * 8] = *(const uint4*)(qp + j * 8);
    }
    // load ctxT: 64 rows x 64 halfs; thread loads half a row
    {
        int r = tid >> 1;
        int hhf = (tid & 1) * 32;
        const __half* cp = g_ctxh + (size_t)bh * 4096 + r * 64 + hhf;
        #pragma unroll
        for (int j = 0; j < 4; ++j)
            *(uint4*)&cs[r * QSTR + hhf + j * 8] = *(const uint4*)(cp + j * 8);
    }
    if (tid < 64) ksum[tid] = g_ksum[bh * 64 + tid];
    __syncthreads();

    // dinv[r] = 1 / sum_d q[r][d]*ksum[d]
    {
        float s = 0.0f;
        #pragma unroll
        for (int d = 0; d < 64; ++d)
            s = fmaf(__half2float(qs[tid * QSTR + d]), ksum[d], s);
        dinv[tid] = 1.0f / s;
    }
    __syncthreads();

    const uint32_t sQ = smem_u32(qs);
    const uint32_t sC = smem_u32(cs);
    const int wm = warp * 32;

    const int blk = lane >> 3;
    const int rib = lane & 7;
    const uint32_t aBase = sQ + (uint32_t)(((wm + (blk & 1) * 8 + rib) * QSTR
                                            + (blk >> 1) * 8) * 2);
    const uint32_t bBase = sC + (uint32_t)((((blk >> 1) * 8 + rib) * QSTR
                                            + (blk & 1) * 8) * 2);

    float acc[2][8][4] = {};

    #pragma unroll
    for (int kk = 0; kk < 64; kk += 16) {
        uint32_t af[2][4];
        #pragma unroll
        for (int mt = 0; mt < 2; ++mt)
            LDM_X4(af[mt][0], af[mt][1], af[mt][2], af[mt][3],
                   aBase + (uint32_t)((mt * 16 * QSTR + kk) * 2));

        uint32_t bf[4][4];
        #pragma unroll
        for (int p = 0; p < 4; ++p)
            LDM_X4(bf[p][0], bf[p][1], bf[p][2], bf[p][3],
                   bBase + (uint32_t)((p * 16 * QSTR + kk) * 2));

        #pragma unroll
        for (int mt = 0; mt < 2; ++mt) {
            #pragma unroll
            for (int p = 0; p < 4; ++p) {
                MMA_F16(acc[mt][2 * p],     af[mt][0], af[mt][1], af[mt][2], af[mt][3],
                        bf[p][0], bf[p][1]);
                MMA_F16(acc[mt][2 * p + 1], af[mt][0], af[mt][1], af[mt][2], af[mt][3],
                        bf[p][2], bf[p][3]);
            }
        }
    }

    // epilogue: out = acc * dinv[row] + q[row][col], fp16 store
    #pragma unroll
    for (int mt = 0; mt < 2; ++mt) {
        const int r0 = wm + mt * 16 + gid;     // local rows r0, r0+8
        const float di0 = dinv[r0];
        const float di1 = dinv[r0 + 8];
        __half* o0 = ah + ((size_t)(b * Tt + t0 + r0)) * Cc + h * 64;
        __half* o1 = ah + ((size_t)(b * Tt + t0 + r0 + 8)) * Cc + h * 64;
        #pragma unroll
        for (int nt = 0; nt < 8; ++nt) {
            const int c0 = nt * 8 + tig * 2;
            float q00 = __half2float(qs[r0 * QSTR + c0]);
            float q01 = __half2float(qs[r0 * QSTR + c0 + 1]);
            float q10 = __half2float(qs[(r0 + 8) * QSTR + c0]);
            float q11 = __half2float(qs[(r0 + 8) * QSTR + c0 + 1]);
            __half2 h0 = __floats2half2_rn(fmaf(acc[mt][nt][0], di0, q00),
                                           fmaf(acc[mt][nt][1], di0, q01));
            __half2 h1 = __floats2half2_rn(fmaf(acc[mt][nt][2], di1, q10),
                                           fmaf(acc[mt][nt][3], di1, q11));
            *(__half2*)(o0 + c0) = h0;
            *(__half2*)(o1 + c0) = h1;
        }
    }
}

// ---------------- launcher ----------------------------------------------------
extern "C" void kernel_launch(void* const* d_in, const int* in_sizes, int n_in,
                              void* d_out, int out_size)
{
    (void)in_sizes; (void)n_in; (void)out_size;

    const float* x  = (const float*)d_in[0];
    const float* Wq = (const float*)d_in[1];
    const float* bq = (const float*)d_in[2];
    const float* Wk = (const float*)d_in[3];
    const float* bk = (const float*)d_in[4];
    const float* Wv = (const float*)d_in[5];
    const float* bv = (const float*)d_in[6];
    const float* Wp = (const float*)d_in[7];
    const float* bp = (const float*)d_in[8];
    float* out = (float*)d_out;

    __half *xh, *qkvh, *ah, *wh;
    float* bcat;
    cudaGetSymbolAddress((void**)&xh, g_xh);
    cudaGetSymbolAddress((void**)&qkvh, g_qkvh);
    cudaGetSymbolAddress((void**)&ah, g_ah);
    cudaGetSymbolAddress((void**)&wh, g_wh);
    cudaGetSymbolAddress((void**)&bcat, g_bcat);

    __half* whq = wh;                              // Wq,Wk,Wv contiguous
    __half* whp = wh + (size_t)3 * Cc * Cc;

    __half* qh = qkvh;
    __half* kh = qkvh + (size_t)Mtot * Cc;
    __half* vh = qkvh + (size_t)2 * Mtot * Cc;

    cudaFuncSetAttribute(gemm_cp, cudaFuncAttributeMaxDynamicSharedMemorySize,
                         GEMM_SMEM_BYTES);
    cudaFuncSetAttribute(attn_out_mma, cudaFuncAttributeMaxDynamicSharedMemorySize,
                         AO_SMEM_BYTES);

    const int xn4 = (Mtot * Cc) / 4;
    const int wn4 = (Cc * Cc) / 4;
    f2h_kernel<<<xn4 / 256, 256>>>(x, xh, xn4);
    f2h_weights<<<(4 * wn4) / 256, 256>>>(Wq, Wk, Wv, Wp, wh, wn4);
    // full coverage of g_ctx (65536 elems)
    pack_bias<<<(Bz * Hh * Dd * Dd + 255) / 256, 256>>>(bq, bk, bv);

    // fused QKV GEMM: N = 3072
    gemm_cp<<<dim3(3 * Cc / GBN, Mtot / GBM), 512, GEMM_SMEM_BYTES>>>(
        xh, whq, bcat, qkvh, nullptr, 1);

    context_mma<<<dim3(CSPLIT, Bz * Hh), 128>>>(kh, vh);
    ctx_finalize<<<(Bz * Hh * Dd * Dd + 255) / 256, 256>>>();

    attn_out_mma<<<dim3(Tt / 128, Hh, Bz), 128, AO_SMEM_BYTES>>>(qh, ah);

    // output projection: N = 1024, fp32 out
    gemm_cp<<<dim3(Cc / GBN, Mtot / GBM), 512, GEMM_SMEM_BYTES>>>(
        ah, whp, bp, nullptr, out, 0);
}